// round 10
// baseline (speedup 1.0000x reference)
#include <cuda_runtime.h>
#include <cuda_bf16.h>
#include <cstdint>
#include <math.h>

#define T_STEPS 32
#define B_SZ    512
#define S_SZ    64
#define F_INDIM 128
#define H1      256
#define H2      256
#define H3      128
#define M_ROWS  (T_STEPS * B_SZ)   // 16384

__device__ __nv_bfloat16 g_spk0[M_ROWS * F_INDIM];
__device__ __nv_bfloat16 g_spk1[M_ROWS * H1];
__device__ __nv_bfloat16 g_spk2[M_ROWS * H2];
__device__ __nv_bfloat16 g_W1s[3 * H1 * F_INDIM];   // [split][h][i]
__device__ __nv_bfloat16 g_W2s[3 * H2 * H1];
__device__ __nv_bfloat16 g_W3s[3 * H3 * H2];

__device__ __forceinline__ uint32_t smem_u32(const void* p) {
    uint32_t a;
    asm("{ .reg .u64 t; cvta.to.shared.u64 t, %1; cvt.u32.u64 %0, t; }" : "=r"(a) : "l"(p));
    return a;
}
__device__ __forceinline__ void ldsm4(uint32_t& r0, uint32_t& r1, uint32_t& r2,
                                      uint32_t& r3, uint32_t addr) {
    asm volatile("ldmatrix.sync.aligned.m8n8.x4.shared.b16 {%0,%1,%2,%3}, [%4];"
                 : "=r"(r0), "=r"(r1), "=r"(r2), "=r"(r3) : "r"(addr));
}
__device__ __forceinline__ void mma16816(float* c, const uint32_t* a,
                                         uint32_t b0, uint32_t b1) {
    asm volatile(
        "mma.sync.aligned.m16n8k16.row.col.f32.bf16.bf16.f32 "
        "{%0,%1,%2,%3}, {%4,%5,%6,%7}, {%8,%9}, {%0,%1,%2,%3};"
        : "+f"(c[0]), "+f"(c[1]), "+f"(c[2]), "+f"(c[3])
        : "r"(a[0]), "r"(a[1]), "r"(a[2]), "r"(a[3]), "r"(b0), "r"(b1));
}
__device__ __forceinline__ void cp16(uint32_t dst, const void* src) {
    asm volatile("cp.async.cg.shared.global [%0], [%1], 16;" :: "r"(dst), "l"(src));
}
#define CP_COMMIT() asm volatile("cp.async.commit_group;" ::: "memory")
#define CP_WAIT(n)  asm volatile("cp.async.wait_group %0;" :: "n"(n) : "memory")

// ---------------------------------------------------------------------------
// Merged encoder + weight-split kernel.
//   blocks [0, 512):   latency encoder (one block per batch element)
//   blocks [512, 768): bf16 3-way weight splits (256 blocks x 512 elems)
//
// Encoder classification: t_idx = rint(logf(d/(d-0.01))*31/TMAX) clipped is a
// monotone binning of d. Per CTA we precompute (double precision) the 31 bin
// boundaries and ambiguity windows; values classify via 5-step binary search,
// and only window-ambiguous values (~1%) evaluate the original float
// expression -> output is bit-identical to the per-value evaluation.
// ---------------------------------------------------------------------------
__global__ void __launch_bounds__(512)
encode_split_kernel(const float* __restrict__ x, __nv_bfloat16* __restrict__ out,
                    const float* __restrict__ W1, const float* __restrict__ W2,
                    const float* __restrict__ W3,
                    __nv_bfloat16* __restrict__ o1, __nv_bfloat16* __restrict__ o2,
                    __nv_bfloat16* __restrict__ o3) {
    const int tid = threadIdx.x;

    // ---------------- weight-split blocks ----------------
    if (blockIdx.x >= 512) {
        const int n1 = H1 * F_INDIM, n2 = H2 * H1, n3 = H3 * H2;
        int idx = (blockIdx.x - 512) * 512 + tid;
        const float* W; __nv_bfloat16* o; int n, i;
        if (idx < n1)                { W = W1; o = o1; n = n1; i = idx; }
        else if (idx < n1 + n2)      { W = W2; o = o2; n = n2; i = idx - n1; }
        else if (idx < n1 + n2 + n3) { W = W3; o = o3; n = n3; i = idx - n1 - n2; }
        else return;
        float w = W[i];
        __nv_bfloat16 h1 = __float2bfloat16_rn(w);
        float r1 = w - __bfloat162float(h1);
        __nv_bfloat16 h2 = __float2bfloat16_rn(r1);
        float r2 = r1 - __bfloat162float(h2);
        o[i] = h1; o[n + i] = h2; o[2 * n + i] = __float2bfloat16_rn(r2);
        return;
    }

    // ---------------- encoder blocks ----------------
    __shared__ float sD[32], sWLO[32], sWHI[32];

    const float TMAX = 11.512935464920229f;   // np.float32(log((0.01+1e-7)/1e-7))

    // Boundary setup (threads 0..31). d(tt) = 0.01*e^{tt*L}/(e^{tt*L}-1),
    // L = TMAX/31 (double). Window: tt in (k+0.5-1e-3, k+0.5+1e-3), widened
    // by 2 ulps each side to also cover float-rounding of the threshold.
    if (tid < 32) {
        if (tid == 31) {
            sD[31] = -1e30f;                   // sentinel for binary search
        } else {
            double L = (double)TMAX / 31.0;
            double tm = (double)tid + 0.5;
            double Em  = exp(tm * L);
            double Ehi = exp((tm + 1e-3) * L);
            double Elo = exp((tm - 1e-3) * L);
            float  Df  = (float)(0.01 * Em  / (Em  - 1.0));
            float  dlo = (float)(0.01 * Ehi / (Ehi - 1.0));   // smaller d
            float  dhi = (float)(0.01 * Elo / (Elo - 1.0));   // larger d
            sD[tid] = Df;
            float wlo = fminf(dlo, Df);
            float whi = fmaxf(dhi, Df);
            wlo = nextafterf(nextafterf(wlo, 0.0f), 0.0f);
            whi = nextafterf(nextafterf(whi, 2.0f), 2.0f);
            sWLO[tid] = wlo;
            sWHI[tid] = whi;
        }
    }
    __syncthreads();

    auto classify = [&](float xn) -> int {
        float d = fmaxf(xn, 0.0100001f);
        int idx = 0;
        idx += (sD[idx + 15] > d) ? 16 : 0;
        idx += (sD[idx + 7]  > d) ? 8  : 0;
        idx += (sD[idx + 3]  > d) ? 4  : 0;
        idx += (sD[idx + 1]  > d) ? 2  : 0;
        idx += (sD[idx]      > d) ? 1  : 0;   // idx = count(D[k] > d) in 0..31
        bool fb = false;
        if (idx > 0)  fb = (d >= sWLO[idx - 1]) && (d <= sWHI[idx - 1]);
        if (idx < 31) fb |= (d >= sWLO[idx]) && (d <= sWHI[idx]);
        if (fb) {   // rare: evaluate the reference float expression verbatim
            float lg = logf(d / (d - 0.01f));
            float tr = rintf((lg * 31.0f) / TMAX);
            tr = fminf(fmaxf(tr, 0.0f), 31.0f);
            idx = (int)tr;
        }
        return idx;
    };

    const int b = blockIdx.x;
    const int f = tid >> 2;
    const int j = tid & 3;

    const float* xp = x + (size_t)b * (S_SZ * F_INDIM) + f;

    float mn = 1e30f, mx = -1e30f;
    unsigned mask = 0;
#pragma unroll
    for (int s = 0; s < 16; ++s) {
        float raw = xp[(j * 16 + s) * F_INDIM];
        float g = (raw < 0.75f) ? 0.0f : raw;
        mn = fminf(mn, g);
        mx = fmaxf(mx, g);
        mask |= (g != 0.0f) ? (1u << s) : 0u;
    }
    mn = fminf(mn, __shfl_xor_sync(0xFFFFFFFFu, mn, 1));
    mn = fminf(mn, __shfl_xor_sync(0xFFFFFFFFu, mn, 2));
    mx = fmaxf(mx, __shfl_xor_sync(0xFFFFFFFFu, mx, 1));
    mx = fmaxf(mx, __shfl_xor_sync(0xFFFFFFFFu, mx, 2));

    float denom = mx - mn + 1e-8f;

    unsigned pk[8];
#pragma unroll
    for (int i = 0; i < 8; ++i) pk[i] = 0u;

    int zc = 16 - __popc(mask);
    if (zc) {
        int t = classify((0.0f - mn) / denom);
        pk[t >> 2] += (unsigned)zc << ((t & 3) * 8);
    }
    while (mask) {
        int s = __ffs(mask) - 1;
        mask &= mask - 1;
        float v = xp[(j * 16 + s) * F_INDIM];   // L1 hit
        int t = classify((v - mn) / denom);
        pk[t >> 2] += 1u << ((t & 3) * 8);
    }

#pragma unroll
    for (int i = 0; i < 8; ++i) {
        pk[i] += __shfl_xor_sync(0xFFFFFFFFu, pk[i], 1);
        pk[i] += __shfl_xor_sync(0xFFFFFFFFu, pk[i], 2);
    }
#pragma unroll
    for (int i = 0; i < 8; ++i) {
        int t = j * 8 + i;
        unsigned c = (pk[t >> 2] >> ((t & 3) * 8)) & 0xFFu;
        out[((size_t)b * T_STEPS + t) * F_INDIM + f] =
            __float2bfloat16_rn((float)c * (1.0f / 64.0f));
    }
}

// ---------------------------------------------------------------------------
// Fused HMMA GEMM + LIF — R9 configuration (proven): tile TM x 128, 512 thr
// (16 warps: 4m x 4n), warp tile (TM/4)m x 32n, MB = TM/64.
// ONESHOT (layer 1): stage all K upfront. Else cp.async 2-stage, K-chunk 64.
// ---------------------------------------------------------------------------
template <int IN, int H, int TM, bool TMAJ, bool ONESHOT>
__global__ void __launch_bounds__(512, 1)
layer_hmma(const __nv_bfloat16* __restrict__ in,
           const __nv_bfloat16* __restrict__ Wsp,
           const float* __restrict__ bias,
           __nv_bfloat16* __restrict__ out_bf,
           float* __restrict__ out_f) {
    constexpr int A_BYTES = TM * 128;
    constexpr int SS      = A_BYTES + 3 * 16384;
    constexpr int MB      = TM / 64;
    constexpr int NCH     = IN / 64;

    extern __shared__ __align__(1024) char smem[];
    const uint32_t sbase = smem_u32(smem);

    const int tid  = threadIdx.x;
    const int lane = tid & 31;
    const int wrp  = tid >> 5;
    const int wm   = wrp & 3;
    const int wn   = wrp >> 2;
    const int r0   = blockIdx.x * TM;
    const int N0   = blockIdx.y * 128;

    const int la_row = lane & 15;
    const int la_ch  = lane >> 4;
    const int lb_row = lane & 7;
    const int lb_ns  = lane >> 4;
    const int lb_ch  = (lane >> 3) & 1;

    int mrow[MB], nrow[2];
#pragma unroll
    for (int mb = 0; mb < MB; ++mb) mrow[mb] = wm * (TM / 4) + mb * 16 + la_row;
#pragma unroll
    for (int p = 0; p < 2; ++p) nrow[p] = wn * 32 + p * 16 + lb_ns * 8 + lb_row;

    const __nv_bfloat16* Ag = in + (size_t)r0 * IN;

    auto issue_stage = [&](int ch, int buf) {
        const uint32_t dstA = sbase + buf * SS;
#pragma unroll
        for (int it = 0; it < TM / 64; ++it) {
            int v = tid + it * 512, m = v >> 3, kv = v & 7;
            uint32_t off = (uint32_t)(m * 128 + kv * 16);
            off ^= (off >> 3) & 0x70;
            cp16(dstA + off, Ag + (size_t)m * IN + ch * 64 + kv * 8);
        }
        const uint32_t dstB = dstA + A_BYTES;
#pragma unroll
        for (int it = 0; it < 6; ++it) {
            int v = tid + it * 512, s = v >> 10, w = v & 1023, n = w >> 3, kv = w & 7;
            uint32_t off = (uint32_t)(n * 128 + kv * 16);
            off ^= (off >> 3) & 0x70;
            cp16(dstB + s * 16384 + off,
                 Wsp + (size_t)s * H * IN + (size_t)(N0 + n) * IN + ch * 64 + kv * 8);
        }
        CP_COMMIT();
    };

    float c[MB][4][4];
#pragma unroll
    for (int mb = 0; mb < MB; ++mb)
#pragma unroll
        for (int nb = 0; nb < 4; ++nb)
#pragma unroll
            for (int q = 0; q < 4; ++q) c[mb][nb][q] = 0.0f;

    auto compute_chunk = [&](uint32_t bufA, uint32_t bufB) {
#pragma unroll
        for (int ks = 0; ks < 4; ++ks) {
            uint32_t a[MB][4];
#pragma unroll
            for (int mb = 0; mb < MB; ++mb) {
                uint32_t off = (uint32_t)(mrow[mb] * 128 +
                               (((ks * 2 + la_ch) * 16) ^ ((mrow[mb] & 7) << 4)));
                ldsm4(a[mb][0], a[mb][1], a[mb][2], a[mb][3], bufA + off);
            }
#pragma unroll
            for (int s = 0; s < 3; ++s) {
#pragma unroll
                for (int p = 0; p < 2; ++p) {
                    uint32_t b0, b1, b2, b3;
                    uint32_t off = (uint32_t)(nrow[p] * 128 +
                                   (((ks * 2 + lb_ch) * 16) ^ ((nrow[p] & 7) << 4)));
                    ldsm4(b0, b1, b2, b3, bufB + s * 16384 + off);
#pragma unroll
                    for (int mb = 0; mb < MB; ++mb) {
                        mma16816(c[mb][2 * p + 0], a[mb], b0, b1);
                        mma16816(c[mb][2 * p + 1], a[mb], b2, b3);
                    }
                }
            }
        }
    };

    if (ONESHOT) {
#pragma unroll
        for (int ch = 0; ch < NCH; ++ch) issue_stage(ch, ch);
        CP_WAIT(0);
        __syncthreads();
#pragma unroll
        for (int ch = 0; ch < NCH; ++ch)
            compute_chunk(sbase + ch * SS, sbase + ch * SS + A_BYTES);
        __syncthreads();
    } else {
        issue_stage(0, 0);
#pragma unroll 1
        for (int ch = 0; ch < NCH; ++ch) {
            if (ch + 1 < NCH) {
                issue_stage(ch + 1, (ch + 1) & 1);
                CP_WAIT(1);
            } else {
                CP_WAIT(0);
            }
            __syncthreads();
            const uint32_t bufA = sbase + (ch & 1) * SS;
            compute_chunk(bufA, bufA + A_BYTES);
            __syncthreads();
        }
    }

    // ---- epilogue: C frags -> smem [TM m][132 stride] f32 ----
    float* scur = (float*)smem;
#pragma unroll
    for (int mb = 0; mb < MB; ++mb)
#pragma unroll
        for (int nb = 0; nb < 4; ++nb) {
            int row = wm * (TM / 4) + mb * 16 + (lane >> 2);
            int col = wn * 32 + nb * 8 + 2 * (lane & 3);
            *(float2*)&scur[(size_t)row * 132 + col] =
                make_float2(c[mb][nb][0], c[mb][nb][1]);
            *(float2*)&scur[(size_t)(row + 8) * 132 + col] =
                make_float2(c[mb][nb][2], c[mb][nb][3]);
        }
    __syncthreads();

    // ---- fused LIF scan ----
#pragma unroll
    for (int task = tid; task < (TM / 32) * 128; task += 512) {
        const int bl = task >> 7;
        const int h  = task & 127;
        const float bv = bias[N0 + h];
        const int bglob = blockIdx.x * (TM / 32) + bl;
        float mem = 0.0f;
#pragma unroll
        for (int t = 0; t < T_STEPS; ++t) {
            float a2  = scur[(size_t)(bl * 32 + t) * 132 + h];
            float cur = __fadd_rn(a2, bv);
            float r   = (mem > 1.0f) ? 1.0f : 0.0f;
            mem = __fsub_rn(__fadd_rn(__fmul_rn(0.9f, mem), cur), r);
            float spk = (mem > 1.0f) ? 1.0f : 0.0f;
            if (TMAJ) {
                out_f[((size_t)t * B_SZ + bglob) * H + N0 + h] = spk;
            } else {
                out_bf[(size_t)(r0 + bl * 32 + t) * H + N0 + h] = __float2bfloat16_rn(spk);
            }
        }
    }
}

// ---------------------------------------------------------------------------
extern "C" void kernel_launch(void* const* d_in, const int* in_sizes, int n_in,
                              void* d_out, int out_size) {
    const float* x  = (const float*)d_in[0];
    const float* W1 = (const float*)d_in[1];
    const float* b1 = (const float*)d_in[2];
    const float* W2 = (const float*)d_in[3];
    const float* b2 = (const float*)d_in[4];
    const float* W3 = (const float*)d_in[5];
    const float* b3 = (const float*)d_in[6];
    float* out = (float*)d_out;

    __nv_bfloat16 *spk0, *spk1, *spk2, *w1s, *w2s, *w3s;
    cudaGetSymbolAddress((void**)&spk0, g_spk0);
    cudaGetSymbolAddress((void**)&spk1, g_spk1);
    cudaGetSymbolAddress((void**)&spk2, g_spk2);
    cudaGetSymbolAddress((void**)&w1s, g_W1s);
    cudaGetSymbolAddress((void**)&w2s, g_W2s);
    cudaGetSymbolAddress((void**)&w3s, g_W3s);

    constexpr int SM256 = 2 * (256 * 128 + 3 * 16384);   // 163840
    constexpr int SM128 = 2 * (128 * 128 + 3 * 16384);   // 131072
    cudaFuncSetAttribute(layer_hmma<F_INDIM, H1, 256, false, true>,
                         cudaFuncAttributeMaxDynamicSharedMemorySize, SM256);
    cudaFuncSetAttribute(layer_hmma<H1, H2, 256, false, false>,
                         cudaFuncAttributeMaxDynamicSharedMemorySize, SM256);
    cudaFuncSetAttribute(layer_hmma<H2, H3, 128, true, false>,
                         cudaFuncAttributeMaxDynamicSharedMemorySize, SM128);

    // encoder (512 blocks) + weight splits (256 blocks), one launch
    encode_split_kernel<<<512 + 256, 512>>>(x, spk0, W1, W2, W3, w1s, w2s, w3s);

    layer_hmma<F_INDIM, H1, 256, false, true>
        <<<dim3(M_ROWS / 256, H1 / 128), 512, SM256>>>(spk0, w1s, b1, spk1, nullptr);
    layer_hmma<H1, H2, 256, false, false>
        <<<dim3(M_ROWS / 256, H2 / 128), 512, SM256>>>(spk1, w2s, b2, spk2, nullptr);
    layer_hmma<H2, H3, 128, true, false>
        <<<dim3(M_ROWS / 128, H3 / 128), 512, SM128>>>(spk2, w3s, b3, nullptr, out);
}

// round 11
// speedup vs baseline: 1.0678x; 1.0678x over previous
#include <cuda_runtime.h>
#include <cuda_bf16.h>
#include <cstdint>

#define T_STEPS 32
#define B_SZ    512
#define S_SZ    64
#define F_INDIM 128
#define H1      256
#define H2      256
#define H3      128
#define M_ROWS  (T_STEPS * B_SZ)   // 16384

__device__ __nv_bfloat16 g_spk0[M_ROWS * F_INDIM];
__device__ __nv_bfloat16 g_spk1[M_ROWS * H1];
__device__ __nv_bfloat16 g_spk2[M_ROWS * H2];
__device__ __nv_bfloat16 g_W1s[3 * H1 * F_INDIM];   // [split][h][i]
__device__ __nv_bfloat16 g_W2s[3 * H2 * H1];
__device__ __nv_bfloat16 g_W3s[3 * H3 * H2];

__device__ __forceinline__ uint32_t smem_u32(const void* p) {
    uint32_t a;
    asm("{ .reg .u64 t; cvta.to.shared.u64 t, %1; cvt.u32.u64 %0, t; }" : "=r"(a) : "l"(p));
    return a;
}
__device__ __forceinline__ void ldsm4(uint32_t& r0, uint32_t& r1, uint32_t& r2,
                                      uint32_t& r3, uint32_t addr) {
    asm volatile("ldmatrix.sync.aligned.m8n8.x4.shared.b16 {%0,%1,%2,%3}, [%4];"
                 : "=r"(r0), "=r"(r1), "=r"(r2), "=r"(r3) : "r"(addr));
}
__device__ __forceinline__ void mma16816(float* c, const uint32_t* a,
                                         uint32_t b0, uint32_t b1) {
    asm volatile(
        "mma.sync.aligned.m16n8k16.row.col.f32.bf16.bf16.f32 "
        "{%0,%1,%2,%3}, {%4,%5,%6,%7}, {%8,%9}, {%0,%1,%2,%3};"
        : "+f"(c[0]), "+f"(c[1]), "+f"(c[2]), "+f"(c[3])
        : "r"(a[0]), "r"(a[1]), "r"(a[2]), "r"(a[3]), "r"(b0), "r"(b1));
}
__device__ __forceinline__ void cp16(uint32_t dst, const void* src) {
    asm volatile("cp.async.cg.shared.global [%0], [%1], 16;" :: "r"(dst), "l"(src));
}
#define CP_COMMIT() asm volatile("cp.async.commit_group;" ::: "memory")
#define CP_WAIT(n)  asm volatile("cp.async.wait_group %0;" :: "n"(n) : "memory")

// ---------------------------------------------------------------------------
// Merged encoder (R6 math, proven fastest) + weight-split kernel.
//   blocks [0, 512):   latency encoder (one block per batch element)
//   blocks [512, 768): bf16 3-way weight splits
// ---------------------------------------------------------------------------
__global__ void __launch_bounds__(512)
encode_split_kernel(const float* __restrict__ x, __nv_bfloat16* __restrict__ out,
                    const float* __restrict__ W1, const float* __restrict__ W2,
                    const float* __restrict__ W3,
                    __nv_bfloat16* __restrict__ o1, __nv_bfloat16* __restrict__ o2,
                    __nv_bfloat16* __restrict__ o3) {
    const int tid = threadIdx.x;

    if (blockIdx.x >= 512) {    // ---- weight-split blocks ----
        const int n1 = H1 * F_INDIM, n2 = H2 * H1, n3 = H3 * H2;
        int idx = (blockIdx.x - 512) * 512 + tid;
        const float* W; __nv_bfloat16* o; int n, i;
        if (idx < n1)                { W = W1; o = o1; n = n1; i = idx; }
        else if (idx < n1 + n2)      { W = W2; o = o2; n = n2; i = idx - n1; }
        else if (idx < n1 + n2 + n3) { W = W3; o = o3; n = n3; i = idx - n1 - n2; }
        else return;
        float w = W[i];
        __nv_bfloat16 h1 = __float2bfloat16_rn(w);
        float r1 = w - __bfloat162float(h1);
        __nv_bfloat16 h2 = __float2bfloat16_rn(r1);
        float r2 = r1 - __bfloat162float(h2);
        o[i] = h1; o[n + i] = h2; o[2 * n + i] = __float2bfloat16_rn(r2);
        return;
    }

    // ---- encoder blocks (R6 version verbatim) ----
    const int b = blockIdx.x;
    const int f = tid >> 2;
    const int j = tid & 3;

    const float* xp = x + (size_t)b * (S_SZ * F_INDIM) + f;

    float mn = 1e30f, mx = -1e30f;
    unsigned mask = 0;
#pragma unroll
    for (int s = 0; s < 16; ++s) {
        float raw = xp[(j * 16 + s) * F_INDIM];
        float g = (raw < 0.75f) ? 0.0f : raw;
        mn = fminf(mn, g);
        mx = fmaxf(mx, g);
        mask |= (g != 0.0f) ? (1u << s) : 0u;
    }
    mn = fminf(mn, __shfl_xor_sync(0xFFFFFFFFu, mn, 1));
    mn = fminf(mn, __shfl_xor_sync(0xFFFFFFFFu, mn, 2));
    mx = fmaxf(mx, __shfl_xor_sync(0xFFFFFFFFu, mx, 1));
    mx = fmaxf(mx, __shfl_xor_sync(0xFFFFFFFFu, mx, 2));

    float denom = mx - mn + 1e-8f;
    const float TMAX = 11.512935464920229f;

    unsigned pk[8];
#pragma unroll
    for (int i = 0; i < 8; ++i) pk[i] = 0u;

    int zc = 16 - __popc(mask);
    if (zc) {
        float xn = (0.0f - mn) / denom;
        float d  = fmaxf(xn, 0.0100001f);
        float lg = logf(d / (d - 0.01f));
        float tr = rintf((lg * 31.0f) / TMAX);
        tr = fminf(fmaxf(tr, 0.0f), 31.0f);
        int t = (int)tr;
        pk[t >> 2] += (unsigned)zc << ((t & 3) * 8);
    }
    while (mask) {
        int s = __ffs(mask) - 1;
        mask &= mask - 1;
        float v  = xp[(j * 16 + s) * F_INDIM];
        float xn = (v - mn) / denom;
        float d  = fmaxf(xn, 0.0100001f);
        float lg = logf(d / (d - 0.01f));
        float tr = rintf((lg * 31.0f) / TMAX);
        tr = fminf(fmaxf(tr, 0.0f), 31.0f);
        int t = (int)tr;
        pk[t >> 2] += 1u << ((t & 3) * 8);
    }

#pragma unroll
    for (int i = 0; i < 8; ++i) {
        pk[i] += __shfl_xor_sync(0xFFFFFFFFu, pk[i], 1);
        pk[i] += __shfl_xor_sync(0xFFFFFFFFu, pk[i], 2);
    }
#pragma unroll
    for (int i = 0; i < 8; ++i) {
        int t = j * 8 + i;
        unsigned c = (pk[t >> 2] >> ((t & 3) * 8)) & 0xFFu;
        out[((size_t)b * T_STEPS + t) * F_INDIM + f] =
            __float2bfloat16_rn((float)c * (1.0f / 64.0f));
    }
}

// ---------------------------------------------------------------------------
// Fused HMMA GEMM + LIF, register-double-buffered software pipeline:
// prefetch next step's B (and A at ks boundaries) before issuing the current
// 16 HMMAs, hiding LDS latency that `asm volatile` otherwise exposes.
// Tile TM x 128, 512 threads (16 warps: 4m x 4n), warp (TM/4)m x 32n.
// ---------------------------------------------------------------------------
template <int IN, int H, int TM, bool TMAJ, bool ONESHOT>
__global__ void __launch_bounds__(512, 1)
layer_hmma(const __nv_bfloat16* __restrict__ in,
           const __nv_bfloat16* __restrict__ Wsp,
           const float* __restrict__ bias,
           __nv_bfloat16* __restrict__ out_bf,
           float* __restrict__ out_f) {
    constexpr int A_BYTES = TM * 128;
    constexpr int SS      = A_BYTES + 3 * 16384;
    constexpr int MB      = TM / 64;
    constexpr int NCH     = IN / 64;

    extern __shared__ __align__(1024) char smem[];
    const uint32_t sbase = smem_u32(smem);

    const int tid  = threadIdx.x;
    const int lane = tid & 31;
    const int wrp  = tid >> 5;
    const int wm   = wrp & 3;
    const int wn   = wrp >> 2;
    const int r0   = blockIdx.x * TM;
    const int N0   = blockIdx.y * 128;

    const int la_row = lane & 15;
    const int la_ch  = lane >> 4;
    const int lb_row = lane & 7;
    const int lb_ns  = lane >> 4;
    const int lb_ch  = (lane >> 3) & 1;

    int mrow[MB], nrow[2];
#pragma unroll
    for (int mb = 0; mb < MB; ++mb) mrow[mb] = wm * (TM / 4) + mb * 16 + la_row;
#pragma unroll
    for (int p = 0; p < 2; ++p) nrow[p] = wn * 32 + p * 16 + lb_ns * 8 + lb_row;

    const __nv_bfloat16* Ag = in + (size_t)r0 * IN;

    auto issue_stage = [&](int ch, int buf) {
        const uint32_t dstA = sbase + buf * SS;
#pragma unroll
        for (int it = 0; it < TM / 64; ++it) {
            int v = tid + it * 512, m = v >> 3, kv = v & 7;
            uint32_t off = (uint32_t)(m * 128 + kv * 16);
            off ^= (off >> 3) & 0x70;
            cp16(dstA + off, Ag + (size_t)m * IN + ch * 64 + kv * 8);
        }
        const uint32_t dstB = dstA + A_BYTES;
#pragma unroll
        for (int it = 0; it < 6; ++it) {
            int v = tid + it * 512, s = v >> 10, w = v & 1023, n = w >> 3, kv = w & 7;
            uint32_t off = (uint32_t)(n * 128 + kv * 16);
            off ^= (off >> 3) & 0x70;
            cp16(dstB + s * 16384 + off,
                 Wsp + (size_t)s * H * IN + (size_t)(N0 + n) * IN + ch * 64 + kv * 8);
        }
        CP_COMMIT();
    };

    float c[MB][4][4];
#pragma unroll
    for (int mb = 0; mb < MB; ++mb)
#pragma unroll
        for (int nb = 0; nb < 4; ++nb)
#pragma unroll
            for (int q = 0; q < 4; ++q) c[mb][nb][q] = 0.0f;

    // Software-pipelined chunk compute: u = ks*3 + s, 12 steps.
    auto compute_chunk = [&](uint32_t bufA, uint32_t bufB) {
        uint32_t aF[2][MB][4];     // double-buffered A frags (per ks parity)
        uint32_t bF[2][2][4];      // double-buffered B frags (per u parity)

        auto loadA = [&](int ks, int pb) {
#pragma unroll
            for (int mb = 0; mb < MB; ++mb) {
                uint32_t off = (uint32_t)(mrow[mb] * 128 +
                               (((ks * 2 + la_ch) * 16) ^ ((mrow[mb] & 7) << 4)));
                ldsm4(aF[pb][mb][0], aF[pb][mb][1], aF[pb][mb][2], aF[pb][mb][3],
                      bufA + off);
            }
        };
        auto loadB = [&](int ks, int s, int pb) {
#pragma unroll
            for (int p = 0; p < 2; ++p) {
                uint32_t off = (uint32_t)(nrow[p] * 128 +
                               (((ks * 2 + lb_ch) * 16) ^ ((nrow[p] & 7) << 4)));
                ldsm4(bF[pb][p][0], bF[pb][p][1], bF[pb][p][2], bF[pb][p][3],
                      bufB + s * 16384 + off);
            }
        };

        loadA(0, 0);
        loadB(0, 0, 0);
#pragma unroll
        for (int u = 0; u < 12; ++u) {
            const int ks = u / 3;
            const int pb = u & 1;
            if (u < 11) {
                const int un = u + 1;
                const int ksn = un / 3, sn = un - ksn * 3;
                loadB(ksn, sn, un & 1);
                if (sn == 0) loadA(ksn, ksn & 1);
            }
#pragma unroll
            for (int p = 0; p < 2; ++p) {
#pragma unroll
                for (int mb = 0; mb < MB; ++mb) {
                    mma16816(c[mb][2 * p + 0], aF[ks & 1][mb], bF[pb][p][0], bF[pb][p][1]);
                    mma16816(c[mb][2 * p + 1], aF[ks & 1][mb], bF[pb][p][2], bF[pb][p][3]);
                }
            }
        }
    };

    if (ONESHOT) {
#pragma unroll
        for (int ch = 0; ch < NCH; ++ch) issue_stage(ch, ch);
        CP_WAIT(0);
        __syncthreads();
#pragma unroll
        for (int ch = 0; ch < NCH; ++ch)
            compute_chunk(sbase + ch * SS, sbase + ch * SS + A_BYTES);
        __syncthreads();
    } else {
        issue_stage(0, 0);
#pragma unroll 1
        for (int ch = 0; ch < NCH; ++ch) {
            if (ch + 1 < NCH) {
                issue_stage(ch + 1, (ch + 1) & 1);
                CP_WAIT(1);
            } else {
                CP_WAIT(0);
            }
            __syncthreads();
            const uint32_t bufA = sbase + (ch & 1) * SS;
            compute_chunk(bufA, bufA + A_BYTES);
            __syncthreads();
        }
    }

    // ---- epilogue: C frags -> smem [TM m][132 stride] f32 ----
    float* scur = (float*)smem;
#pragma unroll
    for (int mb = 0; mb < MB; ++mb)
#pragma unroll
        for (int nb = 0; nb < 4; ++nb) {
            int row = wm * (TM / 4) + mb * 16 + (lane >> 2);
            int col = wn * 32 + nb * 8 + 2 * (lane & 3);
            *(float2*)&scur[(size_t)row * 132 + col] =
                make_float2(c[mb][nb][0], c[mb][nb][1]);
            *(float2*)&scur[(size_t)(row + 8) * 132 + col] =
                make_float2(c[mb][nb][2], c[mb][nb][3]);
        }
    __syncthreads();

    // ---- fused LIF scan ----
#pragma unroll
    for (int task = tid; task < (TM / 32) * 128; task += 512) {
        const int bl = task >> 7;
        const int h  = task & 127;
        const float bv = bias[N0 + h];
        const int bglob = blockIdx.x * (TM / 32) + bl;
        float mem = 0.0f;
#pragma unroll
        for (int t = 0; t < T_STEPS; ++t) {
            float a2  = scur[(size_t)(bl * 32 + t) * 132 + h];
            float cur = __fadd_rn(a2, bv);
            float r   = (mem > 1.0f) ? 1.0f : 0.0f;
            mem = __fsub_rn(__fadd_rn(__fmul_rn(0.9f, mem), cur), r);
            float spk = (mem > 1.0f) ? 1.0f : 0.0f;
            if (TMAJ) {
                out_f[((size_t)t * B_SZ + bglob) * H + N0 + h] = spk;
            } else {
                out_bf[(size_t)(r0 + bl * 32 + t) * H + N0 + h] = __float2bfloat16_rn(spk);
            }
        }
    }
}

// ---------------------------------------------------------------------------
extern "C" void kernel_launch(void* const* d_in, const int* in_sizes, int n_in,
                              void* d_out, int out_size) {
    const float* x  = (const float*)d_in[0];
    const float* W1 = (const float*)d_in[1];
    const float* b1 = (const float*)d_in[2];
    const float* W2 = (const float*)d_in[3];
    const float* b2 = (const float*)d_in[4];
    const float* W3 = (const float*)d_in[5];
    const float* b3 = (const float*)d_in[6];
    float* out = (float*)d_out;

    __nv_bfloat16 *spk0, *spk1, *spk2, *w1s, *w2s, *w3s;
    cudaGetSymbolAddress((void**)&spk0, g_spk0);
    cudaGetSymbolAddress((void**)&spk1, g_spk1);
    cudaGetSymbolAddress((void**)&spk2, g_spk2);
    cudaGetSymbolAddress((void**)&w1s, g_W1s);
    cudaGetSymbolAddress((void**)&w2s, g_W2s);
    cudaGetSymbolAddress((void**)&w3s, g_W3s);

    constexpr int SM256 = 2 * (256 * 128 + 3 * 16384);   // 163840
    constexpr int SM128 = 2 * (128 * 128 + 3 * 16384);   // 131072
    cudaFuncSetAttribute(layer_hmma<F_INDIM, H1, 256, false, true>,
                         cudaFuncAttributeMaxDynamicSharedMemorySize, SM256);
    cudaFuncSetAttribute(layer_hmma<H1, H2, 256, false, false>,
                         cudaFuncAttributeMaxDynamicSharedMemorySize, SM256);
    cudaFuncSetAttribute(layer_hmma<H2, H3, 128, true, false>,
                         cudaFuncAttributeMaxDynamicSharedMemorySize, SM128);

    encode_split_kernel<<<512 + 256, 512>>>(x, spk0, W1, W2, W3, w1s, w2s, w3s);

    layer_hmma<F_INDIM, H1, 256, false, true>
        <<<dim3(M_ROWS / 256, H1 / 128), 512, SM256>>>(spk0, w1s, b1, spk1, nullptr);
    layer_hmma<H1, H2, 256, false, false>
        <<<dim3(M_ROWS / 256, H2 / 128), 512, SM256>>>(spk1, w2s, b2, spk2, nullptr);
    layer_hmma<H2, H3, 128, true, false>
        <<<dim3(M_ROWS / 128, H3 / 128), 512, SM128>>>(spk2, w3s, b3, nullptr, out);
}